// round 2
// baseline (speedup 1.0000x reference)
#include <cuda_runtime.h>
#include <math.h>

#define BB   8192
#define DVV  768
#define NE   8
#define DD   1024
#define GG   2048

// Scratch (static __device__ globals — no allocation allowed)
__device__ float g_combined[BB * GG];          // 64 MB
__device__ float g_gate[BB * NE];              // 256 KB
__device__ float g_h[(size_t)BB * NE * DD];    // 256 MB
__device__ float g_t[(size_t)BB * NE * DD];    // 256 MB

// ---------------------------------------------------------------------------
// Tiled SGEMM: C[m,n] = act( sum_k A[m,k] * B[k,n] + bias[n] )
// 128x128 block tile, BK=8, 8x8 per thread, 256 threads.
// Batched via blockIdx.z with independent strides (expert dimension).
// act: 0 = identity, 1 = exact GELU
// ---------------------------------------------------------------------------
__global__ __launch_bounds__(256, 2)
void sgemm_kernel(const float* __restrict__ A, int lda, long aBatch,
                  const float* __restrict__ Bw, int ldb, long bBatch,
                  const float* __restrict__ bias, long biasBatch,
                  float* __restrict__ C, int ldc, long cBatch,
                  int K, int act)
{
    const int bz = blockIdx.z;
    A    += (long)bz * aBatch;
    Bw   += (long)bz * bBatch;
    bias += (long)bz * biasBatch;
    C    += (long)bz * cBatch;

    __shared__ float As[8][128];
    __shared__ float Bs[8][128];

    const int tid = threadIdx.x;
    const int blockRow = blockIdx.y * 128;
    const int blockCol = blockIdx.x * 128;

    // A tile load mapping: 128 rows x 8 k -> one float4 per thread along K
    const int aRow = tid >> 1;           // 0..127
    const int aK   = (tid & 1) * 4;      // 0 or 4
    // B tile load mapping: 8 k-rows x 128 n -> one float4 per thread along N
    const int bK   = tid >> 5;           // 0..7
    const int bCol = (tid & 31) * 4;     // 0..124

    // Compute mapping: 16x16 thread grid of 8x8 tiles
    const int tCol = (tid & 15) * 8;
    const int tRow = (tid >> 4) * 8;

    float acc[8][8];
    #pragma unroll
    for (int i = 0; i < 8; i++)
        #pragma unroll
        for (int j = 0; j < 8; j++) acc[i][j] = 0.0f;

    const float* aPtr = A + (long)(blockRow + aRow) * lda + aK;
    const float* bPtr = Bw + (long)bK * ldb + blockCol + bCol;

    for (int k0 = 0; k0 < K; k0 += 8) {
        float4 av = *reinterpret_cast<const float4*>(aPtr + k0);
        As[aK + 0][aRow] = av.x;
        As[aK + 1][aRow] = av.y;
        As[aK + 2][aRow] = av.z;
        As[aK + 3][aRow] = av.w;
        float4 bv = *reinterpret_cast<const float4*>(bPtr + (long)k0 * ldb);
        *reinterpret_cast<float4*>(&Bs[bK][bCol]) = bv;
        __syncthreads();

        #pragma unroll
        for (int kk = 0; kk < 8; kk++) {
            float4 a0 = *reinterpret_cast<const float4*>(&As[kk][tRow]);
            float4 a1 = *reinterpret_cast<const float4*>(&As[kk][tRow + 4]);
            float4 b0 = *reinterpret_cast<const float4*>(&Bs[kk][tCol]);
            float4 b1 = *reinterpret_cast<const float4*>(&Bs[kk][tCol + 4]);
            float ar[8] = {a0.x, a0.y, a0.z, a0.w, a1.x, a1.y, a1.z, a1.w};
            float br[8] = {b0.x, b0.y, b0.z, b0.w, b1.x, b1.y, b1.z, b1.w};
            #pragma unroll
            for (int i = 0; i < 8; i++)
                #pragma unroll
                for (int j = 0; j < 8; j++)
                    acc[i][j] = fmaf(ar[i], br[j], acc[i][j]);
        }
        __syncthreads();
    }

    // Epilogue
    float bcol[8];
    #pragma unroll
    for (int j = 0; j < 8; j++) bcol[j] = bias[blockCol + tCol + j];

    #pragma unroll
    for (int i = 0; i < 8; i++) {
        float* cRow = C + (long)(blockRow + tRow + i) * ldc + blockCol + tCol;
        #pragma unroll
        for (int j = 0; j < 8; j++) {
            float v = acc[i][j] + bcol[j];
            if (act == 1)
                v = 0.5f * v * (1.0f + erff(v * 0.70710678118654752f));
            cRow[j] = v;
        }
    }
}

// ---------------------------------------------------------------------------
// Gate: one warp per row. logits = combined[b,:] @ gate_w[2048,8] + gate_b
// then softmax over 8 experts.
// ---------------------------------------------------------------------------
__global__ void gate_kernel(const float* __restrict__ combined,
                            const float* __restrict__ gw,
                            const float* __restrict__ gb,
                            float* __restrict__ gate)
{
    int warp = (blockIdx.x * blockDim.x + threadIdx.x) >> 5;
    int lane = threadIdx.x & 31;
    if (warp >= BB) return;
    const float* row = combined + (long)warp * GG;

    float acc[NE];
    #pragma unroll
    for (int e = 0; e < NE; e++) acc[e] = 0.0f;

    for (int k = lane; k < GG; k += 32) {
        float x = row[k];
        const float4 w0 = *reinterpret_cast<const float4*>(gw + (long)k * NE);
        const float4 w1 = *reinterpret_cast<const float4*>(gw + (long)k * NE + 4);
        acc[0] = fmaf(x, w0.x, acc[0]);
        acc[1] = fmaf(x, w0.y, acc[1]);
        acc[2] = fmaf(x, w0.z, acc[2]);
        acc[3] = fmaf(x, w0.w, acc[3]);
        acc[4] = fmaf(x, w1.x, acc[4]);
        acc[5] = fmaf(x, w1.y, acc[5]);
        acc[6] = fmaf(x, w1.z, acc[6]);
        acc[7] = fmaf(x, w1.w, acc[7]);
    }
    #pragma unroll
    for (int e = 0; e < NE; e++)
        #pragma unroll
        for (int o = 16; o > 0; o >>= 1)
            acc[e] += __shfl_xor_sync(0xFFFFFFFFu, acc[e], o);

    float m = -1e30f;
    #pragma unroll
    for (int e = 0; e < NE; e++) { acc[e] += gb[e]; m = fmaxf(m, acc[e]); }
    float s = 0.0f;
    #pragma unroll
    for (int e = 0; e < NE; e++) { acc[e] = expf(acc[e] - m); s += acc[e]; }
    float inv = 1.0f / s;
    if (lane < NE) gate[(long)warp * NE + lane] = acc[lane] * inv;
}

// ---------------------------------------------------------------------------
// LayerNorm per (b, e) row + gated reduction over experts.
// One block (256 threads) per row b; each thread owns 4 columns.
// ---------------------------------------------------------------------------
__global__ __launch_bounds__(256)
void ln_reduce_kernel(const float* __restrict__ t,
                      const float* __restrict__ gate,
                      const float* __restrict__ ln_g,
                      const float* __restrict__ ln_b,
                      float* __restrict__ out)
{
    const int b = blockIdx.x;
    const int tid = threadIdx.x;
    const int wid = tid >> 5, lane = tid & 31;

    __shared__ float sm_s[8];
    __shared__ float sm_ss[8];

    float o[4] = {0.f, 0.f, 0.f, 0.f};

    for (int e = 0; e < NE; e++) {
        const float* row = t + ((long)b * NE + e) * DD;
        float4 x = *reinterpret_cast<const float4*>(row + tid * 4);
        float s  = x.x + x.y + x.z + x.w;
        float ss = x.x * x.x + x.y * x.y + x.z * x.z + x.w * x.w;
        #pragma unroll
        for (int o2 = 16; o2 > 0; o2 >>= 1) {
            s  += __shfl_xor_sync(0xFFFFFFFFu, s, o2);
            ss += __shfl_xor_sync(0xFFFFFFFFu, ss, o2);
        }
        if (lane == 0) { sm_s[wid] = s; sm_ss[wid] = ss; }
        __syncthreads();
        float ts = 0.f, tss = 0.f;
        #pragma unroll
        for (int w = 0; w < 8; w++) { ts += sm_s[w]; tss += sm_ss[w]; }
        __syncthreads();

        float mu   = ts * (1.0f / DD);
        float var  = tss * (1.0f / DD) - mu * mu;
        float rstd = rsqrtf(var + 1e-5f);
        float p    = gate[(long)b * NE + e];

        const float4 g4 = *reinterpret_cast<const float4*>(ln_g + (long)e * DD + tid * 4);
        const float4 b4 = *reinterpret_cast<const float4*>(ln_b + (long)e * DD + tid * 4);
        const float* xv = &x.x;
        const float* gv = &g4.x;
        const float* bv = &b4.x;
        #pragma unroll
        for (int j = 0; j < 4; j++) {
            float n = (xv[j] - mu) * rstd;
            o[j] = fmaf(p, fmaf(n, gv[j], bv[j]), o[j]);
        }
    }
    *reinterpret_cast<float4*>(out + (long)b * DD + tid * 4) =
        make_float4(o[0], o[1], o[2], o[3]);
}

// ---------------------------------------------------------------------------
// Launch
// ---------------------------------------------------------------------------
extern "C" void kernel_launch(void* const* d_in, const int* in_sizes, int n_in,
                              void* d_out, int out_size)
{
    const float* visual = (const float*)d_in[0];
    const float* text   = (const float*)d_in[1];
    const float* vis_w  = (const float*)d_in[2];
    const float* vis_b  = (const float*)d_in[3];
    const float* txt_w  = (const float*)d_in[4];
    const float* txt_b  = (const float*)d_in[5];
    const float* gate_w = (const float*)d_in[6];
    const float* gate_b = (const float*)d_in[7];
    const float* w1     = (const float*)d_in[8];
    const float* b1     = (const float*)d_in[9];
    const float* w2     = (const float*)d_in[10];
    const float* b2     = (const float*)d_in[11];
    const float* ln_g   = (const float*)d_in[12];
    const float* ln_b   = (const float*)d_in[13];
    float* out = (float*)d_out;

    float *combined, *gate, *h, *t;
    cudaGetSymbolAddress((void**)&combined, g_combined);
    cudaGetSymbolAddress((void**)&gate, g_gate);
    cudaGetSymbolAddress((void**)&h, g_h);
    cudaGetSymbolAddress((void**)&t, g_t);

    dim3 blk(256);

    // 1) Projections -> combined [8192, 2048]
    dim3 gProj(DD / 128, BB / 128, 1);
    sgemm_kernel<<<gProj, blk>>>(visual, DVV, 0, vis_w, DD, 0, vis_b, 0,
                                 combined, GG, 0, DVV, 0);
    sgemm_kernel<<<gProj, blk>>>(text, DVV, 0, txt_w, DD, 0, txt_b, 0,
                                 combined + DD, GG, 0, DVV, 0);

    // 2) Gate softmax
    gate_kernel<<<(BB * 32) / 256, blk>>>(combined, gate_w, gate_b, gate);

    // 3) Expert GEMM1 + GELU: h[b,e,d]
    dim3 gE1(DD / 128, BB / 128, NE);
    sgemm_kernel<<<gE1, blk>>>(combined, GG, 0,
                               w1, DD, (long)GG * DD,
                               b1, DD,
                               h, NE * DD, DD,
                               GG, 1);

    // 4) Expert GEMM2: t[b,e,d]
    dim3 gE2(DD / 128, BB / 128, NE);
    sgemm_kernel<<<gE2, blk>>>(h, NE * DD, DD,
                               w2, DD, (long)DD * DD,
                               b2, DD,
                               t, NE * DD, DD,
                               DD, 0);

    // 5) LayerNorm + gated reduce -> out [8192, 1024]
    ln_reduce_kernel<<<BB, blk>>>(t, gate, ln_g, ln_b, out);
}

// round 4
// speedup vs baseline: 3.6014x; 3.6014x over previous
#include <cuda_runtime.h>
#include <math.h>
#include <cstdint>

#define BB   8192
#define DVV  768
#define NE   8
#define DD   1024
#define GG   2048

// GEMM tiling
#define BM 128
#define BN 256
#define BK 32
#define STAGES 3
#define PADK 36                        // floats per smem row (32 + 4 pad)
#define STAGE_FLOATS ((BM + BN) * PADK)
#define SMEM_BYTES (STAGES * STAGE_FLOATS * 4)

// ---------------------------------------------------------------------------
// Scratch (static device globals)
// ---------------------------------------------------------------------------
__device__ float g_visr[(size_t)BB * DVV];
__device__ float g_txtr[(size_t)BB * DVV];
__device__ float g_viswT[(size_t)DVV * DD];
__device__ float g_txtwT[(size_t)DVV * DD];
__device__ float g_w1T[(size_t)NE * GG * DD];   // [e][n=DD][k=GG]
__device__ float g_w2T[(size_t)NE * DD * DD];   // [e][n=DD][k=DD]
__device__ float g_combined[(size_t)BB * GG];
__device__ float g_gate[BB * NE];
__device__ float g_h[(size_t)BB * NE * DD];
__device__ float g_t[(size_t)BB * NE * DD];

// ---------------------------------------------------------------------------
// Helpers
// ---------------------------------------------------------------------------
__device__ __forceinline__ float rna_tf32(float x) {
    uint32_t u;
    asm("cvt.rna.tf32.f32 %0, %1;" : "=r"(u) : "f"(x));
    return __uint_as_float(u);
}
__device__ __forceinline__ uint32_t smem_u32(const void* p) {
    uint32_t a;
    asm("{ .reg .u64 t; cvta.to.shared.u64 t, %1; cvt.u32.u64 %0, t; }" : "=r"(a) : "l"(p));
    return a;
}
__device__ __forceinline__ void cp_async16(uint32_t dst, const float* src) {
    asm volatile("cp.async.cg.shared.global [%0], [%1], 16;" :: "r"(dst), "l"(src));
}
#define CP_COMMIT() asm volatile("cp.async.commit_group;" ::: "memory")
#define CP_WAIT(n)  asm volatile("cp.async.wait_group %0;" :: "n"(n) : "memory")

__device__ __forceinline__ void mma_tf32(float& c0, float& c1, float& c2, float& c3,
                                         uint32_t a0, uint32_t a1, uint32_t a2, uint32_t a3,
                                         uint32_t b0, uint32_t b1) {
    asm volatile(
        "mma.sync.aligned.m16n8k8.row.col.f32.tf32.tf32.f32 "
        "{%0,%1,%2,%3}, {%4,%5,%6,%7}, {%8,%9}, {%0,%1,%2,%3};\n"
        : "+f"(c0), "+f"(c1), "+f"(c2), "+f"(c3)
        : "r"(a0), "r"(a1), "r"(a2), "r"(a3), "r"(b0), "r"(b1));
}

// ---------------------------------------------------------------------------
// tf32 tensor-core GEMM: C[m,n] = act( sum_k A[m,k]*B[n,k] + bias[n] )
// A row-major [M,K] (tf32-rounded fp32), B [N,K] K-major (tf32-rounded fp32).
// CTA 128x256, warp 64x64 (2x4 warps), BK=32, 3-stage cp.async pipeline.
// mode 0: store rna(v)        (projections -> combined)
// mode 1: store rna(gelu(v))  (expert GEMM1 -> h)
// mode 2: store v             (expert GEMM2 -> t)
// ---------------------------------------------------------------------------
__global__ __launch_bounds__(256, 1)
void tf32_gemm(const float* __restrict__ A, long aBatch, int lda,
               const float* __restrict__ B, long bBatch, int ldb,
               const float* __restrict__ bias, long biasBatch,
               int K, int mode,
               float* __restrict__ C, long cBatch, int ldc, int colOfs)
{
    extern __shared__ float smem[];
    const int tid  = threadIdx.x;
    const int wid  = tid >> 5;
    const int lane = tid & 31;
    const int e    = blockIdx.z;
    const int blockRow = blockIdx.y * BM;
    const int blockCol = blockIdx.x * BN;

    A    += (long)e * aBatch;
    B    += (long)e * bBatch;
    bias += (long)e * biasBatch;
    C    += (long)e * cBatch;

    const float* Ag = A + (long)blockRow * lda;
    const float* Bg = B + (long)blockCol * ldb;

    const uint32_t smem_base = smem_u32(smem);

    // warp grid: 2 (m) x 4 (n); warp tile 64x64
    const int warpRow = (wid & 1) * 64;
    const int warpCol = (wid >> 1) * 64;
    const int groupID = lane >> 2;
    const int ctig    = lane & 3;

    float acc[4][8][4];
    #pragma unroll
    for (int i = 0; i < 4; i++)
        #pragma unroll
        for (int j = 0; j < 8; j++)
            #pragma unroll
            for (int r = 0; r < 4; r++) acc[i][j][r] = 0.0f;

    const int NC = K / BK;

    // ---- async stage loader ----
    // A: 1024 16B-chunks (m 0..127, kc 0..7) -> 4/thread
    // B: 2048 16B-chunks (n 0..255, kc 0..7) -> 8/thread
    auto load_stage = [&](int stage, int chunk) {
        const int k0 = chunk * BK;
        const uint32_t aBase = smem_base + (uint32_t)(stage * STAGE_FLOATS) * 4u;
        const uint32_t bBase = aBase + (uint32_t)(BM * PADK) * 4u;
        #pragma unroll
        for (int i = 0; i < 4; i++) {
            int id = tid + i * 256;
            int m = id >> 3, kc = id & 7;
            cp_async16(aBase + (uint32_t)(m * PADK + kc * 4) * 4u,
                       Ag + (long)m * lda + k0 + kc * 4);
        }
        #pragma unroll
        for (int i = 0; i < 8; i++) {
            int id = tid + i * 256;
            int n = id >> 3, kc = id & 7;
            cp_async16(bBase + (uint32_t)(n * PADK + kc * 4) * 4u,
                       Bg + (long)n * ldb + k0 + kc * 4);
        }
        CP_COMMIT();
    };

    // prologue
    #pragma unroll
    for (int s = 0; s < STAGES - 1; s++) load_stage(s, s);
    CP_WAIT(STAGES - 2);
    __syncthreads();

    for (int c = 0; c < NC; c++) {
        if (c + STAGES - 1 < NC)
            load_stage((c + STAGES - 1) % STAGES, c + STAGES - 1);

        const int stage = c % STAGES;
        const uint32_t* As = reinterpret_cast<const uint32_t*>(smem + stage * STAGE_FLOATS);
        const uint32_t* Bs = As + BM * PADK;

        #pragma unroll
        for (int kk = 0; kk < 4; kk++) {
            uint32_t a[4][4], b[8][2];
            const int kb = kk * 8;
            #pragma unroll
            for (int i = 0; i < 4; i++) {
                const uint32_t* p = As + (warpRow + i * 16 + groupID) * PADK + kb + ctig;
                a[i][0] = p[0];
                a[i][1] = p[8 * PADK];
                a[i][2] = p[4];
                a[i][3] = p[8 * PADK + 4];
            }
            #pragma unroll
            for (int j = 0; j < 8; j++) {
                const uint32_t* p = Bs + (warpCol + j * 8 + groupID) * PADK + kb + ctig;
                b[j][0] = p[0];
                b[j][1] = p[4];
            }
            #pragma unroll
            for (int i = 0; i < 4; i++)
                #pragma unroll
                for (int j = 0; j < 8; j++)
                    mma_tf32(acc[i][j][0], acc[i][j][1], acc[i][j][2], acc[i][j][3],
                             a[i][0], a[i][1], a[i][2], a[i][3],
                             b[j][0], b[j][1]);
        }

        CP_WAIT(STAGES - 2);
        __syncthreads();
    }

    // ---- epilogue ----
    #pragma unroll
    for (int i = 0; i < 4; i++) {
        const int r0 = blockRow + warpRow + i * 16 + groupID;
        #pragma unroll
        for (int j = 0; j < 8; j++) {
            const int col = warpCol + j * 8 + ctig * 2;       // within [0, BN)
            const int gc  = blockCol + col;                   // within [0, N)
            const float b0 = bias[gc], b1 = bias[gc + 1];
            float v0 = acc[i][j][0] + b0;
            float v1 = acc[i][j][1] + b1;
            float v2 = acc[i][j][2] + b0;
            float v3 = acc[i][j][3] + b1;
            if (mode == 1) {
                v0 = 0.5f * v0 * (1.0f + erff(v0 * 0.70710678118654752f));
                v1 = 0.5f * v1 * (1.0f + erff(v1 * 0.70710678118654752f));
                v2 = 0.5f * v2 * (1.0f + erff(v2 * 0.70710678118654752f));
                v3 = 0.5f * v3 * (1.0f + erff(v3 * 0.70710678118654752f));
            }
            if (mode != 2) {
                v0 = rna_tf32(v0); v1 = rna_tf32(v1);
                v2 = rna_tf32(v2); v3 = rna_tf32(v3);
            }
            float* c0p = C + (long)r0 * ldc + colOfs + gc;
            float* c1p = C + (long)(r0 + 8) * ldc + colOfs + gc;
            *reinterpret_cast<float2*>(c0p) = make_float2(v0, v1);
            *reinterpret_cast<float2*>(c1p) = make_float2(v2, v3);
        }
    }
}

// ---------------------------------------------------------------------------
// fp32 -> tf32-rounded fp32 copy
// ---------------------------------------------------------------------------
__global__ void round_copy_kernel(const float* __restrict__ x,
                                  float* __restrict__ y, long n)
{
    long i = ((long)blockIdx.x * blockDim.x + threadIdx.x) * 4;
    if (i >= n) return;
    float4 v = *reinterpret_cast<const float4*>(x + i);
    v.x = rna_tf32(v.x); v.y = rna_tf32(v.y);
    v.z = rna_tf32(v.z); v.w = rna_tf32(v.w);
    *reinterpret_cast<float4*>(y + i) = v;
}

// ---------------------------------------------------------------------------
// W [K,N] fp32 -> WT [N,K] tf32-rounded (batched over z)
// ---------------------------------------------------------------------------
__global__ __launch_bounds__(256)
void transpose_round_kernel(const float* __restrict__ W,
                            float* __restrict__ WT, int K, int N)
{
    __shared__ float tile[32][33];
    const int e = blockIdx.z;
    W  += (long)e * K * N;
    WT += (long)e * K * N;
    const int n0 = blockIdx.x * 32, k0 = blockIdx.y * 32;
    const int tx = threadIdx.x & 31, ty = threadIdx.x >> 5;

    #pragma unroll
    for (int r = 0; r < 4; r++)
        tile[ty + r * 8][tx] = W[(long)(k0 + ty + r * 8) * N + n0 + tx];
    __syncthreads();
    #pragma unroll
    for (int r = 0; r < 4; r++) {
        int n = n0 + ty + r * 8, k = k0 + tx;
        WT[(long)n * K + k] = rna_tf32(tile[tx][ty + r * 8]);
    }
}

// ---------------------------------------------------------------------------
// Gate: one warp per row
// ---------------------------------------------------------------------------
__global__ void gate_kernel(const float* __restrict__ combined,
                            const float* __restrict__ gw,
                            const float* __restrict__ gb,
                            float* __restrict__ gate)
{
    int warp = (blockIdx.x * blockDim.x + threadIdx.x) >> 5;
    int lane = threadIdx.x & 31;
    if (warp >= BB) return;
    const float* row = combined + (long)warp * GG;

    float acc[NE];
    #pragma unroll
    for (int e = 0; e < NE; e++) acc[e] = 0.0f;

    for (int k = lane; k < GG; k += 32) {
        float x = row[k];
        const float4 w0 = *reinterpret_cast<const float4*>(gw + (long)k * NE);
        const float4 w1 = *reinterpret_cast<const float4*>(gw + (long)k * NE + 4);
        acc[0] = fmaf(x, w0.x, acc[0]);
        acc[1] = fmaf(x, w0.y, acc[1]);
        acc[2] = fmaf(x, w0.z, acc[2]);
        acc[3] = fmaf(x, w0.w, acc[3]);
        acc[4] = fmaf(x, w1.x, acc[4]);
        acc[5] = fmaf(x, w1.y, acc[5]);
        acc[6] = fmaf(x, w1.z, acc[6]);
        acc[7] = fmaf(x, w1.w, acc[7]);
    }
    #pragma unroll
    for (int e = 0; e < NE; e++)
        #pragma unroll
        for (int o = 16; o > 0; o >>= 1)
            acc[e] += __shfl_xor_sync(0xFFFFFFFFu, acc[e], o);

    float m = -1e30f;
    #pragma unroll
    for (int e = 0; e < NE; e++) { acc[e] += gb[e]; m = fmaxf(m, acc[e]); }
    float s = 0.0f;
    #pragma unroll
    for (int e = 0; e < NE; e++) { acc[e] = expf(acc[e] - m); s += acc[e]; }
    float inv = 1.0f / s;
    if (lane < NE) gate[(long)warp * NE + lane] = acc[lane] * inv;
}

// ---------------------------------------------------------------------------
// LayerNorm per (b,e) row + gated reduction over experts
// ---------------------------------------------------------------------------
__global__ __launch_bounds__(256)
void ln_reduce_kernel(const float* __restrict__ t,
                      const float* __restrict__ gate,
                      const float* __restrict__ ln_g,
                      const float* __restrict__ ln_b,
                      float* __restrict__ out)
{
    const int b = blockIdx.x;
    const int tid = threadIdx.x;
    const int wid = tid >> 5, lane = tid & 31;

    __shared__ float sm_s[8];
    __shared__ float sm_ss[8];

    float o[4] = {0.f, 0.f, 0.f, 0.f};

    for (int e = 0; e < NE; e++) {
        const float* row = t + ((long)b * NE + e) * DD;
        float4 x = *reinterpret_cast<const float4*>(row + tid * 4);
        float s  = x.x + x.y + x.z + x.w;
        float ss = x.x * x.x + x.y * x.y + x.z * x.z + x.w * x.w;
        #pragma unroll
        for (int o2 = 16; o2 > 0; o2 >>= 1) {
            s  += __shfl_xor_sync(0xFFFFFFFFu, s, o2);
            ss += __shfl_xor_sync(0xFFFFFFFFu, ss, o2);
        }
        if (lane == 0) { sm_s[wid] = s; sm_ss[wid] = ss; }
        __syncthreads();
        float ts = 0.f, tss = 0.f;
        #pragma unroll
        for (int w = 0; w < 8; w++) { ts += sm_s[w]; tss += sm_ss[w]; }
        __syncthreads();

        float mu   = ts * (1.0f / DD);
        float var  = tss * (1.0f / DD) - mu * mu;
        float rstd = rsqrtf(var + 1e-5f);
        float p    = gate[(long)b * NE + e];

        const float4 g4 = *reinterpret_cast<const float4*>(ln_g + (long)e * DD + tid * 4);
        const float4 b4 = *reinterpret_cast<const float4*>(ln_b + (long)e * DD + tid * 4);
        const float* xv = &x.x;
        const float* gv = &g4.x;
        const float* bv = &b4.x;
        #pragma unroll
        for (int j = 0; j < 4; j++) {
            float n = (xv[j] - mu) * rstd;
            o[j] = fmaf(p, fmaf(n, gv[j], bv[j]), o[j]);
        }
    }
    *reinterpret_cast<float4*>(out + (long)b * DD + tid * 4) =
        make_float4(o[0], o[1], o[2], o[3]);
}

// ---------------------------------------------------------------------------
// Launch
// ---------------------------------------------------------------------------
extern "C" void kernel_launch(void* const* d_in, const int* in_sizes, int n_in,
                              void* d_out, int out_size)
{
    const float* visual = (const float*)d_in[0];
    const float* text   = (const float*)d_in[1];
    const float* vis_w  = (const float*)d_in[2];
    const float* vis_b  = (const float*)d_in[3];
    const float* txt_w  = (const float*)d_in[4];
    const float* txt_b  = (const float*)d_in[5];
    const float* gate_w = (const float*)d_in[6];
    const float* gate_b = (const float*)d_in[7];
    const float* w1     = (const float*)d_in[8];
    const float* b1     = (const float*)d_in[9];
    const float* w2     = (const float*)d_in[10];
    const float* b2     = (const float*)d_in[11];
    const float* ln_g   = (const float*)d_in[12];
    const float* ln_b   = (const float*)d_in[13];
    float* out = (float*)d_out;

    float *visr, *txtr, *viswT, *txtwT, *w1T, *w2T, *combined, *gate, *h, *t;
    cudaGetSymbolAddress((void**)&visr, g_visr);
    cudaGetSymbolAddress((void**)&txtr, g_txtr);
    cudaGetSymbolAddress((void**)&viswT, g_viswT);
    cudaGetSymbolAddress((void**)&txtwT, g_txtwT);
    cudaGetSymbolAddress((void**)&w1T, g_w1T);
    cudaGetSymbolAddress((void**)&w2T, g_w2T);
    cudaGetSymbolAddress((void**)&combined, g_combined);
    cudaGetSymbolAddress((void**)&gate, g_gate);
    cudaGetSymbolAddress((void**)&h, g_h);
    cudaGetSymbolAddress((void**)&t, g_t);

    cudaFuncSetAttribute(tf32_gemm, cudaFuncAttributeMaxDynamicSharedMemorySize, SMEM_BYTES);

    // 1) prep: round inputs, transpose+round weights
    {
        long n = (long)BB * DVV;
        int blocks = (int)((n / 4 + 255) / 256);
        round_copy_kernel<<<blocks, 256>>>(visual, visr, n);
        round_copy_kernel<<<blocks, 256>>>(text,   txtr, n);
    }
    transpose_round_kernel<<<dim3(DD/32, DVV/32, 1), 256>>>(vis_w, viswT, DVV, DD);
    transpose_round_kernel<<<dim3(DD/32, DVV/32, 1), 256>>>(txt_w, txtwT, DVV, DD);
    transpose_round_kernel<<<dim3(DD/32, GG/32, NE), 256>>>(w1, w1T, GG, DD);
    transpose_round_kernel<<<dim3(DD/32, DD/32, NE), 256>>>(w2, w2T, DD, DD);

    // 2) projections -> combined [8192, 2048] (tf32-rounded fp32)
    {
        dim3 g(DD / BN, BB / BM, 1);
        tf32_gemm<<<g, 256, SMEM_BYTES>>>(visr, 0, DVV, viswT, 0, DVV,
                                          vis_b, 0, DVV, 0,
                                          combined, 0, GG, 0);
        tf32_gemm<<<g, 256, SMEM_BYTES>>>(txtr, 0, DVV, txtwT, 0, DVV,
                                          txt_b, 0, DVV, 0,
                                          combined, 0, GG, DD);
    }

    // 3) gate softmax
    gate_kernel<<<(BB * 32) / 256, 256>>>(combined, gate_w, gate_b, gate);

    // 4) expert GEMM1 + GELU -> h
    {
        dim3 g(DD / BN, BB / BM, NE);
        tf32_gemm<<<g, 256, SMEM_BYTES>>>(combined, 0, GG,
                                          w1T, (long)GG * DD, GG,
                                          b1, DD, GG, 1,
                                          h, DD, NE * DD, 0);
    }

    // 5) expert GEMM2 -> t
    {
        dim3 g(DD / BN, BB / BM, NE);
        tf32_gemm<<<g, 256, SMEM_BYTES>>>(h, DD, NE * DD,
                                          w2T, (long)DD * DD, DD,
                                          b2, DD, DD, 2,
                                          t, DD, NE * DD, 0);
    }

    // 6) LayerNorm + gated reduce -> out
    ln_reduce_kernel<<<BB, 256>>>(t, gate, ln_g, ln_b, out);
}